// round 1
// baseline (speedup 1.0000x reference)
#include <cuda_runtime.h>
#include <math.h>

#define BB 4
#define CF 16
#define CLIPS 7
#define DC 256
#define KC 8192

// ---------------- scratch (device globals; no allocation) ----------------
__device__ float g_y1[BB*32*CF*96*96];   // conv1 out
__device__ float g_p1[BB*32*CF*48*48];   // pool1 out
__device__ float g_y2[BB*64*CF*48*48];   // conv2 out
__device__ float g_p2[BB*64*CF*24*24];   // pool2 out
__device__ float g_y3[BB*128*CF*24*24];  // conv3 out
__device__ float g_h [BB*32768];         // flattened encoder features (per clip)
__device__ float g_feat[BB*CLIPS*DC];
__device__ float g_quant[BB*CLIPS*DC];
__device__ int   g_tok[BB*CLIPS];
__device__ double g_stats[2*128];
__device__ float g_scale[128];
__device__ float g_shift[128];
__device__ float g_part_s[28*32];
__device__ int   g_part_i[28*32];
__device__ float g_gx[BB*6*768];
__device__ float g_gh[BB*768];
__device__ float g_hst[BB*DC];
__device__ float g_ctx[BB*6*DC];
__device__ float g_scal[2];

// ---------------- direct conv3d, k=3, pad=1, NCDHW ----------------
// block: (WS/PW, TH) threads; grid: (HS/TH, COUT/COT, B*CF)
template<int CIN, int COUT, int HS, int WS, int TH, int PW, int COT>
__global__ void conv3d_k(const float* __restrict__ xin, long sn, long sc, long sd,
                         const float* __restrict__ w, const float* __restrict__ bias,
                         float* __restrict__ y)
{
    constexpr int WP = WS + 2;
    constexpr int NT = (WS/PW)*TH;
    __shared__ float s_x[(TH+2)*WP];
    __shared__ float s_w[COT*9];
    const int tx = threadIdx.x, ty = threadIdx.y;
    const int tid = ty*(WS/PW) + tx;
    const int nd = blockIdx.z;
    const int n = nd >> 4, d = nd & 15;
    const int h0 = blockIdx.x * TH;
    const int co0 = blockIdx.y * COT;

    float acc[COT][PW];
    #pragma unroll
    for (int co=0; co<COT; co++)
        #pragma unroll
        for (int p=0; p<PW; p++) acc[co][p] = 0.f;

    #pragma unroll 1
    for (int ci=0; ci<CIN; ci++) {
        #pragma unroll 1
        for (int kd=0; kd<3; kd++) {
            int din = d + kd - 1;
            if (din < 0 || din >= CF) continue;           // uniform across block
            __syncthreads();
            const float* xp = xin + (long)n*sn + (long)ci*sc + (long)din*sd;
            for (int i = tid; i < (TH+2)*WP; i += NT) {
                int r = i / WP, c = i - r*WP;
                int hh = h0 + r - 1, ww = c - 1;
                float v = 0.f;
                if (hh >= 0 && hh < HS && (unsigned)ww < (unsigned)WS) v = xp[hh*WS + ww];
                s_x[i] = v;
            }
            for (int i = tid; i < COT*9; i += NT) {
                int co = i / 9, k = i - co*9;
                s_w[i] = w[((long)(co0+co)*CIN + ci)*27 + kd*9 + k];
            }
            __syncthreads();
            #pragma unroll
            for (int kh=0; kh<3; kh++) {
                float xr[PW+2];
                #pragma unroll
                for (int p=0; p<PW+2; p++)
                    xr[p] = s_x[(ty+kh)*WP + tx*PW + p];
                #pragma unroll
                for (int kw=0; kw<3; kw++) {
                    #pragma unroll
                    for (int co=0; co<COT; co++) {
                        float wv = s_w[co*9 + kh*3 + kw];
                        #pragma unroll
                        for (int p=0; p<PW; p++)
                            acc[co][p] = fmaf(wv, xr[p+kw], acc[co][p]);
                    }
                }
            }
        }
    }
    const int h = h0 + ty;
    #pragma unroll
    for (int co=0; co<COT; co++) {
        float bv = bias[co0+co];
        long base = (((long)n*COUT + co0+co)*CF + d)*(HS*WS) + h*WS + tx*PW;
        #pragma unroll
        for (int p=0; p<PW; p++) y[base+p] = acc[co][p] + bv;
    }
}

// ---------------- BN stats ----------------
__global__ void zero_stats_k(int C) {
    int i = threadIdx.x;
    if (i < 2*C) g_stats[i] = 0.0;
}

__global__ void stats_k(const float* __restrict__ y, int C, int planeN)
{
    int c = blockIdx.x;
    float s = 0.f, s2 = 0.f;
    for (int n=0; n<BB; n++) {
        const float* p = y + (long)(n*C + c)*planeN;
        for (int i = blockIdx.y*blockDim.x + threadIdx.x; i < planeN; i += gridDim.y*blockDim.x) {
            float v = p[i];
            s += v;
            s2 = fmaf(v, v, s2);
        }
    }
    __shared__ double sh[256];
    __shared__ double sh2[256];
    sh[threadIdx.x] = (double)s; sh2[threadIdx.x] = (double)s2;
    __syncthreads();
    for (int o=128; o>0; o>>=1) {
        if (threadIdx.x < o) { sh[threadIdx.x] += sh[threadIdx.x+o]; sh2[threadIdx.x] += sh2[threadIdx.x+o]; }
        __syncthreads();
    }
    if (threadIdx.x == 0) {
        atomicAdd(&g_stats[c],   sh[0]);
        atomicAdd(&g_stats[C+c], sh2[0]);
    }
}

__global__ void finalize_stats_k(const float* __restrict__ gma, const float* __restrict__ bet,
                                 int C, double cnt)
{
    int c = threadIdx.x;
    if (c < C) {
        double m = g_stats[c] / cnt;
        double v = g_stats[C+c] / cnt - m*m;
        double sc = (double)gma[c] / sqrt(v + 1e-5);
        g_scale[c] = (float)sc;
        g_shift[c] = (float)((double)bet[c] - m*sc);
    }
}

// ---------------- BN + ReLU + maxpool(1,2,2) ----------------
__global__ void bn_maxpool_k(const float* __restrict__ y, float* __restrict__ out,
                             int C, int H, int W)
{
    int HO = H/2, WO = W/2;
    int total = BB*C*CF*HO*WO;
    for (int o = blockIdx.x*blockDim.x + threadIdx.x; o < total; o += gridDim.x*blockDim.x) {
        int wo = o % WO; int t = o / WO;
        int ho = t % HO; t /= HO;
        int d  = t % CF; t /= CF;
        int c  = t % C;  int n = t / C;
        float sc = g_scale[c], sh = g_shift[c];
        const float* p = y + (((long)(n*C+c)*CF + d)*H + 2*ho)*W + 2*wo;
        float a0 = fmaxf(fmaf(sc, p[0],   sh), 0.f);
        float a1 = fmaxf(fmaf(sc, p[1],   sh), 0.f);
        float a2 = fmaxf(fmaf(sc, p[W],   sh), 0.f);
        float a3 = fmaxf(fmaf(sc, p[W+1], sh), 0.f);
        out[o] = fmaxf(fmaxf(a0,a1), fmaxf(a2,a3));
    }
}

// ---------------- BN + ReLU + avgpool 6x6 -> flattened h ----------------
__global__ void bn_avgpool_k(const float* __restrict__ y)
{
    int idx = blockIdx.x*blockDim.x + threadIdx.x;   // 131072 total
    if (idx >= BB*128*CF*16) return;
    int wo = idx & 3; int t = idx >> 2;
    int ho = t & 3;  t >>= 2;
    int d  = t & 15; t >>= 4;
    int c  = t & 127; int n = t >> 7;
    float sc = g_scale[c], sh = g_shift[c];
    const float* p = y + (((long)(n*128+c)*CF + d)*24 + 6*ho)*24 + 6*wo;
    float s = 0.f;
    #pragma unroll
    for (int i=0;i<6;i++)
        #pragma unroll
        for (int j=0;j<6;j++)
            s += fmaxf(fmaf(sc, p[i*24+j], sh), 0.f);
    g_h[(long)n*32768 + c*256 + d*16 + ho*4 + wo] = s * (1.f/36.f);
}

// ---------------- projection: feat = h @ pw^T + pb ----------------
__global__ void proj_k(const float* __restrict__ pw, const float* __restrict__ pb, int clip)
{
    int bco = blockIdx.x;            // 0..1023
    int b_ = bco >> 8, co = bco & 255;
    const float* hrow = g_h + (long)b_*32768;
    const float* wrow = pw + (long)co*32768;
    float a = 0.f;
    for (int j = threadIdx.x; j < 32768; j += 128)
        a = fmaf(hrow[j], wrow[j], a);
    __shared__ float sh[128];
    sh[threadIdx.x] = a; __syncthreads();
    for (int o=64; o>0; o>>=1) {
        if (threadIdx.x < o) sh[threadIdx.x] += sh[threadIdx.x+o];
        __syncthreads();
    }
    if (threadIdx.x == 0)
        g_feat[((long)b_*CLIPS + clip)*DC + co] = sh[0] + pb[co];
}

// ---------------- VQ argmin ----------------
__global__ void quant_score_k(const float* __restrict__ cb)
{
    int row = blockIdx.x;                        // 0..27
    int k = blockIdx.y*256 + threadIdx.x;        // code index
    __shared__ float sf[DC];
    sf[threadIdx.x] = g_feat[row*DC + threadIdx.x];
    __syncthreads();
    const float4* c4 = (const float4*)(cb + (long)k*DC);
    const float4* f4 = (const float4*)sf;
    float dot = 0.f, cn = 0.f;
    #pragma unroll 8
    for (int j=0; j<64; j++) {
        float4 c = c4[j]; float4 f = f4[j];
        dot = fmaf(c.x,f.x,dot); dot = fmaf(c.y,f.y,dot);
        dot = fmaf(c.z,f.z,dot); dot = fmaf(c.w,f.w,dot);
        cn  = fmaf(c.x,c.x,cn);  cn  = fmaf(c.y,c.y,cn);
        cn  = fmaf(c.z,c.z,cn);  cn  = fmaf(c.w,c.w,cn);
    }
    float score = cn - 2.f*dot;
    __shared__ float ss[256];
    __shared__ int   si[256];
    ss[threadIdx.x] = score; si[threadIdx.x] = k;
    __syncthreads();
    for (int o=128; o>0; o>>=1) {
        if (threadIdx.x < o) {
            float s2 = ss[threadIdx.x+o]; int i2 = si[threadIdx.x+o];
            if (s2 < ss[threadIdx.x] || (s2 == ss[threadIdx.x] && i2 < si[threadIdx.x])) {
                ss[threadIdx.x] = s2; si[threadIdx.x] = i2;
            }
        }
        __syncthreads();
    }
    if (threadIdx.x == 0) { g_part_s[row*32+blockIdx.y] = ss[0]; g_part_i[row*32+blockIdx.y] = si[0]; }
}

__global__ void quant_reduce_k(const float* __restrict__ cb)
{
    int row = blockIdx.x;
    __shared__ int bi;
    if (threadIdx.x == 0) {
        float s = g_part_s[row*32]; int i = g_part_i[row*32];
        for (int j=1; j<32; j++) {
            float s2 = g_part_s[row*32+j]; int i2 = g_part_i[row*32+j];
            if (s2 < s || (s2 == s && i2 < i)) { s = s2; i = i2; }
        }
        g_tok[row] = i; bi = i;
    }
    __syncthreads();
    const float* crow = cb + (long)bi*DC;
    for (int j = threadIdx.x; j < DC; j += blockDim.x)
        g_quant[row*DC+j] = crow[j];
}

// ---------------- losses ----------------
__global__ void commit_loss_k()
{
    float s = 0.f;
    for (int i = threadIdx.x; i < BB*CLIPS*DC; i += blockDim.x) {
        float d = g_feat[i] - g_quant[i];
        s = fmaf(d, d, s);
    }
    __shared__ float sh[256];
    sh[threadIdx.x] = s; __syncthreads();
    for (int o=128; o>0; o>>=1) { if (threadIdx.x<o) sh[threadIdx.x]+=sh[threadIdx.x+o]; __syncthreads(); }
    if (threadIdx.x == 0) g_scal[0] = sh[0] / (float)(BB*CLIPS*DC);
}

__global__ void ctx_loss_k()
{
    float s = 0.f;
    for (int i = threadIdx.x; i < BB*6*DC; i += blockDim.x) {
        int d = i % DC; int t = (i/DC) % 6; int b_ = i/(6*DC);
        float diff = g_ctx[i] - g_feat[(b_*CLIPS + t + 1)*DC + d];
        s = fmaf(diff, diff, s);
    }
    __shared__ float sh[256];
    sh[threadIdx.x] = s; __syncthreads();
    for (int o=128; o>0; o>>=1) { if (threadIdx.x<o) sh[threadIdx.x]+=sh[threadIdx.x+o]; __syncthreads(); }
    if (threadIdx.x == 0) g_scal[1] = sh[0] / (float)(BB*6*DC);
}

// ---------------- GRU ----------------
__global__ void gru_gx_k(const float* __restrict__ wih, const float* __restrict__ bih)
{
    int bt = blockIdx.x;                       // b*6+t
    int g = blockIdx.y*128 + threadIdx.x;      // 0..767
    int b_ = bt/6, t = bt%6;
    __shared__ float sq[DC];
    sq[threadIdx.x]     = g_quant[(b_*CLIPS+t)*DC + threadIdx.x];
    sq[threadIdx.x+128] = g_quant[(b_*CLIPS+t)*DC + 128 + threadIdx.x];
    __syncthreads();
    const float4* w4 = (const float4*)(wih + (long)g*DC);
    const float4* q4 = (const float4*)sq;
    float a = bih[g];
    #pragma unroll 8
    for (int j=0;j<64;j++) {
        float4 w = w4[j], q = q4[j];
        a = fmaf(w.x,q.x,a); a = fmaf(w.y,q.y,a); a = fmaf(w.z,q.z,a); a = fmaf(w.w,q.w,a);
    }
    g_gx[bt*768 + g] = a;
}

__global__ void zero_h_k() {
    int i = blockIdx.x*blockDim.x + threadIdx.x;
    if (i < BB*DC) g_hst[i] = 0.f;
}

__global__ void gru_gh_k(const float* __restrict__ whh, const float* __restrict__ bhh)
{
    int b_ = blockIdx.x;
    int g = blockIdx.y*128 + threadIdx.x;
    __shared__ float shh[DC];
    shh[threadIdx.x]     = g_hst[b_*DC + threadIdx.x];
    shh[threadIdx.x+128] = g_hst[b_*DC + 128 + threadIdx.x];
    __syncthreads();
    const float4* w4 = (const float4*)(whh + (long)g*DC);
    const float4* h4 = (const float4*)shh;
    float a = bhh[g];
    #pragma unroll 8
    for (int j=0;j<64;j++) {
        float4 w = w4[j], h = h4[j];
        a = fmaf(w.x,h.x,a); a = fmaf(w.y,h.y,a); a = fmaf(w.z,h.z,a); a = fmaf(w.w,h.w,a);
    }
    g_gh[b_*768 + g] = a;
}

__global__ void gru_gate_k(int t)
{
    int b_ = blockIdx.x, d = threadIdx.x;
    int bt = b_*6 + t;
    float xr = g_gx[bt*768 + d];
    float xz = g_gx[bt*768 + 256 + d];
    float xn = g_gx[bt*768 + 512 + d];
    float hr = g_gh[b_*768 + d];
    float hz = g_gh[b_*768 + 256 + d];
    float hn = g_gh[b_*768 + 512 + d];
    float r = 1.f/(1.f + expf(-(xr+hr)));
    float z = 1.f/(1.f + expf(-(xz+hz)));
    float nn = tanhf(xn + r*hn);
    float h = g_hst[b_*DC + d];
    float h2 = (1.f - z)*nn + z*h;
    g_hst[b_*DC + d] = h2;
    g_ctx[bt*DC + d] = h2;
}

// ---------------- output assembly ----------------
__global__ void finalize_k(float* __restrict__ out)
{
    int tid = threadIdx.x;
    for (int i = tid; i < BB*CLIPS; i += blockDim.x) out[i] = (float)g_tok[i];
    for (int i = tid; i < BB*CLIPS*DC; i += blockDim.x) out[28 + i] = g_quant[i];
    if (tid == 0) {
        float c = g_scal[0], x = g_scal[1];
        out[28 + 7168 + 0] = c;            // commitment
        out[28 + 7168 + 1] = c;            // codebook (value-identical)
        out[28 + 7168 + 2] = x;            // context
        out[28 + 7168 + 3] = c + 0.25f*c + 0.1f*x;
    }
}

// ---------------- host launcher ----------------
extern "C" void kernel_launch(void* const* d_in, const int* in_sizes, int n_in,
                              void* d_out, int out_size)
{
    const float* x   = (const float*)d_in[0];
    const float* c1w = (const float*)d_in[1];
    const float* c1b = (const float*)d_in[2];
    const float* g1  = (const float*)d_in[3];
    const float* b1  = (const float*)d_in[4];
    const float* c2w = (const float*)d_in[5];
    const float* c2b = (const float*)d_in[6];
    const float* g2  = (const float*)d_in[7];
    const float* b2  = (const float*)d_in[8];
    const float* c3w = (const float*)d_in[9];
    const float* c3b = (const float*)d_in[10];
    const float* g3  = (const float*)d_in[11];
    const float* b3  = (const float*)d_in[12];
    const float* pw  = (const float*)d_in[13];
    const float* pb  = (const float*)d_in[14];
    const float* cb  = (const float*)d_in[15];
    const float* wih = (const float*)d_in[16];
    const float* whh = (const float*)d_in[17];
    const float* bih = (const float*)d_in[18];
    const float* bhh = (const float*)d_in[19];
    float* out = (float*)d_out;

    float *y1, *p1, *y2, *p2, *y3;
    cudaGetSymbolAddress((void**)&y1, g_y1);
    cudaGetSymbolAddress((void**)&p1, g_p1);
    cudaGetSymbolAddress((void**)&y2, g_y2);
    cudaGetSymbolAddress((void**)&p2, g_p2);
    cudaGetSymbolAddress((void**)&y3, g_y3);

    for (int clip = 0; clip < CLIPS; clip++) {
        // conv1: [4,3,16,96,96] -> [4,32,16,96,96]
        conv3d_k<3,32,96,96,8,6,8><<<dim3(12,4,64), dim3(16,8)>>>(
            x + (long)clip*8*96*96, (long)3*64*96*96, (long)64*96*96, (long)96*96,
            c1w, c1b, y1);
        zero_stats_k<<<1,256>>>(32);
        stats_k<<<dim3(32,32),256>>>(y1, 32, 16*96*96);
        finalize_stats_k<<<1,128>>>(g1, b1, 32, (double)(BB*16*96*96));
        bn_maxpool_k<<<2048,256>>>(y1, p1, 32, 96, 96);

        // conv2: [4,32,16,48,48] -> [4,64,16,48,48]
        conv3d_k<32,64,48,48,16,6,8><<<dim3(3,8,64), dim3(8,16)>>>(
            p1, (long)32*16*48*48, (long)16*48*48, (long)48*48, c2w, c2b, y2);
        zero_stats_k<<<1,256>>>(64);
        stats_k<<<dim3(64,16),256>>>(y2, 64, 16*48*48);
        finalize_stats_k<<<1,128>>>(g2, b2, 64, (double)(BB*16*48*48));
        bn_maxpool_k<<<1024,256>>>(y2, p2, 64, 48, 48);

        // conv3: [4,64,16,24,24] -> [4,128,16,24,24]
        conv3d_k<64,128,24,24,24,6,8><<<dim3(1,16,64), dim3(4,24)>>>(
            p2, (long)64*16*24*24, (long)16*24*24, (long)24*24, c3w, c3b, y3);
        zero_stats_k<<<1,256>>>(128);
        stats_k<<<dim3(128,8),256>>>(y3, 128, 16*24*24);
        finalize_stats_k<<<1,128>>>(g3, b3, 128, (double)(BB*16*24*24));
        bn_avgpool_k<<<512,256>>>(y3);

        proj_k<<<1024,128>>>(pw, pb, clip);
    }

    quant_score_k<<<dim3(28,32),256>>>(cb);
    quant_reduce_k<<<28,64>>>(cb);
    commit_loss_k<<<1,256>>>();

    gru_gx_k<<<dim3(24,6),128>>>(wih, bih);
    zero_h_k<<<4,256>>>();
    for (int t = 0; t < 6; t++) {
        gru_gh_k<<<dim3(4,6),128>>>(whh, bhh);
        gru_gate_k<<<4,256>>>(t);
    }
    ctx_loss_k<<<1,256>>>();
    finalize_k<<<1,256>>>(out);
}

// round 3
// speedup vs baseline: 1.1174x; 1.1174x over previous
#include <cuda_runtime.h>
#include <math.h>

#define BB 4
#define CF 16
#define CLIPS 7
#define DC 256
#define KC 8192

typedef unsigned long long u64;

__device__ __forceinline__ u64 pk2(float lo, float hi) {
    u64 r; asm("mov.b64 %0,{%1,%2};" : "=l"(r) : "f"(lo), "f"(hi)); return r;
}
__device__ __forceinline__ void upk2(u64 v, float& lo, float& hi) {
    asm("mov.b64 {%0,%1},%2;" : "=f"(lo), "=f"(hi) : "l"(v));
}
__device__ __forceinline__ u64 fma2(u64 a, u64 b, u64 c) {
    u64 r; asm("fma.rn.f32x2 %0,%1,%2,%3;" : "=l"(r) : "l"(a), "l"(b), "l"(c)); return r;
}

// ---------------- scratch (device globals; no allocation) ----------------
__device__ float g_y1[CLIPS*BB*32*CF*96*96];   // conv1 out
__device__ float g_p1[CLIPS*BB*32*CF*48*48];   // pool1 out
__device__ float g_y2[CLIPS*BB*64*CF*48*48];   // conv2 out
__device__ float g_p2[CLIPS*BB*64*CF*24*24];   // pool2 out
__device__ float g_y3[CLIPS*BB*128*CF*24*24];  // conv3 out
__device__ float g_h [CLIPS*BB*32768];         // encoder features, row r=clip*4+b
__device__ float g_feat[BB*CLIPS*DC];
__device__ float g_quant[BB*CLIPS*DC];
__device__ int   g_tok[BB*CLIPS];
__device__ double g_stats[3*CLIPS*256];        // [stage][clip][sum|sumsq]
__device__ float g_scale[CLIPS*128];
__device__ float g_shift[CLIPS*128];
__device__ float g_part_s[28*32];
__device__ int   g_part_i[28*32];
__device__ float g_gx[BB*6*768];
__device__ float g_gh[BB*768];
__device__ float g_hst[BB*DC];
__device__ float g_ctx[BB*6*DC];
__device__ float g_scal[2];

// ---------------- direct conv3d, k=3, pad=1, f32x2 packed FMA ----------------
// block: (WS/PW, TH); grid: (HS/TH, COUT/COT, CLIPS*BB*CF)
template<int CIN, int COUT, int HS, int WS, int TH, int PW, int COT>
__global__ void conv3d_k(const float* __restrict__ xin, long sclip, long sn, long sc, long sd,
                         int doff, const float* __restrict__ w, const float* __restrict__ bias,
                         float* __restrict__ y)
{
    constexpr int WP = WS + 2;
    constexpr int NT = (WS/PW)*TH;
    constexpr int PH = PW/2;
    __shared__ __align__(16) float s_x[(TH+2)*WP];
    __shared__ __align__(16) float s_w2[COT*9*2];
    const int tx = threadIdx.x, ty = threadIdx.y;
    const int tid = ty*(WS/PW) + tx;
    const int nd = blockIdx.z;
    const int clip = nd >> 6;          // BB*CF = 64
    const int n = (nd >> 4) & 3, d = nd & 15;
    const int h0 = blockIdx.x * TH;
    const int co0 = blockIdx.y * COT;

    u64 acc2[COT][PH];
    #pragma unroll
    for (int co=0; co<COT; co++)
        #pragma unroll
        for (int j=0; j<PH; j++) acc2[co][j] = 0ULL;

    #pragma unroll 1
    for (int ci=0; ci<CIN; ci++) {
        #pragma unroll 1
        for (int kd=0; kd<3; kd++) {
            int din = d + kd - 1;
            if (din < 0 || din >= CF) continue;          // uniform across block
            __syncthreads();
            const float* xp = xin + (long)clip*sclip + (long)n*sn + (long)ci*sc
                                  + (long)(clip*doff + din)*sd;
            for (int i = tid; i < (TH+2)*WP; i += NT) {
                int r = i / WP, c = i - r*WP;
                int hh = h0 + r - 1, ww = c - 1;
                float v = 0.f;
                if (hh >= 0 && hh < HS && (unsigned)ww < (unsigned)WS) v = xp[hh*WS + ww];
                s_x[i] = v;
            }
            for (int i = tid; i < COT*9; i += NT) {
                int co = i / 9, k = i - co*9;
                float wv = w[((long)(co0+co)*CIN + ci)*27 + kd*9 + k];
                s_w2[2*i] = wv; s_w2[2*i+1] = wv;
            }
            __syncthreads();
            #pragma unroll
            for (int kh=0; kh<3; kh++) {
                const float* xr = &s_x[(ty+kh)*WP + tx*PW];
                float f0=xr[0], f1=xr[1], f2=xr[2], f3=xr[3];
                float f4=xr[4], f5=xr[5], f6=xr[6], f7=xr[7];
                u64 e0=pk2(f0,f1), e1=pk2(f2,f3), e2=pk2(f4,f5), e3=pk2(f6,f7);
                u64 o0=pk2(f1,f2), o1=pk2(f3,f4), o2=pk2(f5,f6);
                #pragma unroll
                for (int co=0; co<COT; co++) {
                    u64 w0 = *(const u64*)&s_w2[2*(co*9 + kh*3 + 0)];
                    acc2[co][0] = fma2(w0, e0, acc2[co][0]);
                    acc2[co][1] = fma2(w0, e1, acc2[co][1]);
                    acc2[co][2] = fma2(w0, e2, acc2[co][2]);
                    u64 w1 = *(const u64*)&s_w2[2*(co*9 + kh*3 + 1)];
                    acc2[co][0] = fma2(w1, o0, acc2[co][0]);
                    acc2[co][1] = fma2(w1, o1, acc2[co][1]);
                    acc2[co][2] = fma2(w1, o2, acc2[co][2]);
                    u64 w2 = *(const u64*)&s_w2[2*(co*9 + kh*3 + 2)];
                    acc2[co][0] = fma2(w2, e1, acc2[co][0]);
                    acc2[co][1] = fma2(w2, e2, acc2[co][1]);
                    acc2[co][2] = fma2(w2, e3, acc2[co][2]);
                }
            }
        }
    }
    const int h = h0 + ty;
    #pragma unroll
    for (int co=0; co<COT; co++) {
        float bv = bias[co0+co];
        long base = (((long)(clip*BB+n)*COUT + co0+co)*CF + d)*(HS*WS) + h*WS + tx*PW;
        #pragma unroll
        for (int j=0; j<PH; j++) {
            float lo, hi; upk2(acc2[co][j], lo, hi);
            y[base + 2*j]     = lo + bv;
            y[base + 2*j + 1] = hi + bv;
        }
    }
}

// ---------------- BN stats (batched over clips; per-stage regions) ----------------
__global__ void zero_stats_k() {
    int i = blockIdx.x*blockDim.x + threadIdx.x;
    if (i < 3*CLIPS*256) g_stats[i] = 0.0;
}

__global__ void stats_k(const float* __restrict__ y, int stage, int C, int planeN,
                        long nstride, long clipstride)
{
    int cc = blockIdx.x;
    int clip = cc / C, c = cc - clip*C;
    float s = 0.f, s2 = 0.f;
    const float* base = y + (long)clip*clipstride + (long)c*planeN;
    for (int n=0; n<BB; n++) {
        const float* p = base + (long)n*nstride;
        for (int i = blockIdx.y*blockDim.x + threadIdx.x; i < planeN; i += gridDim.y*blockDim.x) {
            float v = p[i];
            s += v;
            s2 = fmaf(v, v, s2);
        }
    }
    __shared__ double sh[256];
    __shared__ double sh2[256];
    sh[threadIdx.x] = (double)s; sh2[threadIdx.x] = (double)s2;
    __syncthreads();
    for (int o=128; o>0; o>>=1) {
        if (threadIdx.x < o) { sh[threadIdx.x] += sh[threadIdx.x+o]; sh2[threadIdx.x] += sh2[threadIdx.x+o]; }
        __syncthreads();
    }
    if (threadIdx.x == 0) {
        double* st = g_stats + (long)stage*CLIPS*256;
        atomicAdd(&st[clip*256 + c],       sh[0]);
        atomicAdd(&st[clip*256 + 128 + c], sh2[0]);
    }
}

__global__ void finalize_stats_k(const float* __restrict__ gma, const float* __restrict__ bet,
                                 int stage, int C, double cnt)
{
    int clip = blockIdx.x, c = threadIdx.x;
    if (c < C) {
        const double* st = g_stats + (long)stage*CLIPS*256;
        double m = st[clip*256 + c] / cnt;
        double v = st[clip*256 + 128 + c] / cnt - m*m;
        double sc = (double)gma[c] / sqrt(v + 1e-5);
        g_scale[clip*128 + c] = (float)sc;
        g_shift[clip*128 + c] = (float)((double)bet[c] - m*sc);
    }
}

// ---------------- BN + ReLU + maxpool(1,2,2), batched ----------------
__global__ void bn_maxpool_k(const float* __restrict__ y, float* __restrict__ out,
                             int C, int H, int W)
{
    int HO = H/2, WO = W/2;
    long total = (long)CLIPS*BB*C*CF*HO*WO;
    for (long o = (long)blockIdx.x*blockDim.x + threadIdx.x; o < total; o += (long)gridDim.x*blockDim.x) {
        int wo = o % WO; long t = o / WO;
        int ho = t % HO; t /= HO;
        int d  = t % CF; t /= CF;
        int c  = t % C;  t /= C;
        int n  = t % BB; int clip = t / BB;
        float sc = g_scale[clip*128 + c], sh = g_shift[clip*128 + c];
        const float* p = y + (((long)((clip*BB+n)*C + c)*CF + d)*H + 2*ho)*W + 2*wo;
        float a0 = fmaxf(fmaf(sc, p[0],   sh), 0.f);
        float a1 = fmaxf(fmaf(sc, p[1],   sh), 0.f);
        float a2 = fmaxf(fmaf(sc, p[W],   sh), 0.f);
        float a3 = fmaxf(fmaf(sc, p[W+1], sh), 0.f);
        out[o] = fmaxf(fmaxf(a0,a1), fmaxf(a2,a3));
    }
}

// ---------------- BN + ReLU + avgpool 6x6 -> flattened h, batched ----------------
__global__ void bn_avgpool_k(const float* __restrict__ y)
{
    int idx = blockIdx.x*blockDim.x + threadIdx.x;   // 917504 total
    if (idx >= CLIPS*BB*128*16*16) return;
    int wo = idx & 3;
    int ho = (idx >> 2) & 3;
    int d  = (idx >> 4) & 15;
    int c  = (idx >> 8) & 127;
    int n  = (idx >> 15) & 3;
    int clip = idx >> 17;
    float sc = g_scale[clip*128 + c], sh = g_shift[clip*128 + c];
    const float* p = y + ((((long)(clip*BB+n)*128 + c)*CF + d)*24 + 6*ho)*24 + 6*wo;
    float s = 0.f;
    #pragma unroll
    for (int i=0;i<6;i++)
        #pragma unroll
        for (int j=0;j<6;j++)
            s += fmaxf(fmaf(sc, p[i*24+j], sh), 0.f);
    g_h[(long)(clip*BB+n)*32768 + c*256 + d*16 + ho*4 + wo] = s * (1.f/36.f);
}

// ---------------- batched projection: one block per output code ----------------
__global__ void proj_k(const float* __restrict__ pw, const float* __restrict__ pb)
{
    int co = blockIdx.x;
    int t = threadIdx.x;
    float part[28];
    #pragma unroll
    for (int r=0;r<28;r++) part[r] = 0.f;
    const float* wrow = pw + (long)co*32768;
    for (int j = t; j < 32768; j += 256) {
        float wv = wrow[j];
        #pragma unroll
        for (int r=0;r<28;r++)
            part[r] = fmaf(wv, g_h[(long)r*32768 + j], part[r]);
    }
    #pragma unroll
    for (int r=0;r<28;r++)
        #pragma unroll
        for (int o=16;o>0;o>>=1)
            part[r] += __shfl_xor_sync(0xffffffff, part[r], o);
    __shared__ float sred[28][8];
    int wa = t >> 5, l = t & 31;
    if (l == 0) {
        #pragma unroll
        for (int r=0;r<28;r++) sred[r][wa] = part[r];
    }
    __syncthreads();
    if (t < 28) {
        float a = 0.f;
        #pragma unroll
        for (int k=0;k<8;k++) a += sred[t][k];
        int clip = t >> 2, b_ = t & 3;
        g_feat[(b_*CLIPS + clip)*DC + co] = a + pb[co];
    }
}

// ---------------- VQ argmin ----------------
__global__ void quant_score_k(const float* __restrict__ cb)
{
    int row = blockIdx.x;                        // 0..27
    int k = blockIdx.y*256 + threadIdx.x;        // code index
    __shared__ float sf[DC];
    sf[threadIdx.x] = g_feat[row*DC + threadIdx.x];
    __syncthreads();
    const float4* c4 = (const float4*)(cb + (long)k*DC);
    const float4* f4 = (const float4*)sf;
    float dot = 0.f, cn = 0.f;
    #pragma unroll 8
    for (int j=0; j<64; j++) {
        float4 c = c4[j]; float4 f = f4[j];
        dot = fmaf(c.x,f.x,dot); dot = fmaf(c.y,f.y,dot);
        dot = fmaf(c.z,f.z,dot); dot = fmaf(c.w,f.w,dot);
        cn  = fmaf(c.x,c.x,cn);  cn  = fmaf(c.y,c.y,cn);
        cn  = fmaf(c.z,c.z,cn);  cn  = fmaf(c.w,c.w,cn);
    }
    float score = cn - 2.f*dot;
    __shared__ float ss[256];
    __shared__ int   si[256];
    ss[threadIdx.x] = score; si[threadIdx.x] = k;
    __syncthreads();
    for (int o=128; o>0; o>>=1) {
        if (threadIdx.x < o) {
            float s2 = ss[threadIdx.x+o]; int i2 = si[threadIdx.x+o];
            if (s2 < ss[threadIdx.x] || (s2 == ss[threadIdx.x] && i2 < si[threadIdx.x])) {
                ss[threadIdx.x] = s2; si[threadIdx.x] = i2;
            }
        }
        __syncthreads();
    }
    if (threadIdx.x == 0) { g_part_s[row*32+blockIdx.y] = ss[0]; g_part_i[row*32+blockIdx.y] = si[0]; }
}

__global__ void quant_reduce_k(const float* __restrict__ cb)
{
    int row = blockIdx.x;
    __shared__ int bi;
    if (threadIdx.x == 0) {
        float s = g_part_s[row*32]; int i = g_part_i[row*32];
        for (int j=1; j<32; j++) {
            float s2 = g_part_s[row*32+j]; int i2 = g_part_i[row*32+j];
            if (s2 < s || (s2 == s && i2 < i)) { s = s2; i = i2; }
        }
        g_tok[row] = i; bi = i;
    }
    __syncthreads();
    const float* crow = cb + (long)bi*DC;
    for (int j = threadIdx.x; j < DC; j += blockDim.x)
        g_quant[row*DC+j] = crow[j];
}

// ---------------- losses ----------------
__global__ void commit_loss_k()
{
    float s = 0.f;
    for (int i = threadIdx.x; i < BB*CLIPS*DC; i += blockDim.x) {
        float d = g_feat[i] - g_quant[i];
        s = fmaf(d, d, s);
    }
    __shared__ float sh[256];
    sh[threadIdx.x] = s; __syncthreads();
    for (int o=128; o>0; o>>=1) { if (threadIdx.x<o) sh[threadIdx.x]+=sh[threadIdx.x+o]; __syncthreads(); }
    if (threadIdx.x == 0) g_scal[0] = sh[0] / (float)(BB*CLIPS*DC);
}

__global__ void ctx_loss_k()
{
    float s = 0.f;
    for (int i = threadIdx.x; i < BB*6*DC; i += blockDim.x) {
        int d = i % DC; int t = (i/DC) % 6; int b_ = i/(6*DC);
        float diff = g_ctx[i] - g_feat[(b_*CLIPS + t + 1)*DC + d];
        s = fmaf(diff, diff, s);
    }
    __shared__ float sh[256];
    sh[threadIdx.x] = s; __syncthreads();
    for (int o=128; o>0; o>>=1) { if (threadIdx.x<o) sh[threadIdx.x]+=sh[threadIdx.x+o]; __syncthreads(); }
    if (threadIdx.x == 0) g_scal[1] = sh[0] / (float)(BB*6*DC);
}

// ---------------- GRU ----------------
__global__ void gru_gx_k(const float* __restrict__ wih, const float* __restrict__ bih)
{
    int bt = blockIdx.x;                       // b*6+t
    int g = blockIdx.y*128 + threadIdx.x;      // 0..767
    int b_ = bt/6, t = bt%6;
    __shared__ float sq[DC];
    sq[threadIdx.x]     = g_quant[(b_*CLIPS+t)*DC + threadIdx.x];
    sq[threadIdx.x+128] = g_quant[(b_*CLIPS+t)*DC + 128 + threadIdx.x];
    __syncthreads();
    const float4* w4 = (const float4*)(wih + (long)g*DC);
    const float4* q4 = (const float4*)sq;
    float a = bih[g];
    #pragma unroll 8
    for (int j=0;j<64;j++) {
        float4 w = w4[j], q = q4[j];
        a = fmaf(w.x,q.x,a); a = fmaf(w.y,q.y,a); a = fmaf(w.z,q.z,a); a = fmaf(w.w,q.w,a);
    }
    g_gx[bt*768 + g] = a;
}

__global__ void zero_h_k() {
    int i = blockIdx.x*blockDim.x + threadIdx.x;
    if (i < BB*DC) g_hst[i] = 0.f;
}

__global__ void gru_gh_k(const float* __restrict__ whh, const float* __restrict__ bhh)
{
    int b_ = blockIdx.x;
    int g = blockIdx.y*128 + threadIdx.x;
    __shared__ float shh[DC];
    shh[threadIdx.x]     = g_hst[b_*DC + threadIdx.x];
    shh[threadIdx.x+128] = g_hst[b_*DC + 128 + threadIdx.x];
    __syncthreads();
    const float4* w4 = (const float4*)(whh + (long)g*DC);
    const float4* h4 = (const float4*)shh;
    float a = bhh[g];
    #pragma unroll 8
    for (int j=0;j<64;j++) {
        float4 w = w4[j], h = h4[j];
        a = fmaf(w.x,h.x,a); a = fmaf(w.y,h.y,a); a = fmaf(w.z,h.z,a); a = fmaf(w.w,h.w,a);
    }
    g_gh[b_*768 + g] = a;
}

__global__ void gru_gate_k(int t)
{
    int b_ = blockIdx.x, d = threadIdx.x;
    int bt = b_*6 + t;
    float xr = g_gx[bt*768 + d];
    float xz = g_gx[bt*768 + 256 + d];
    float xn = g_gx[bt*768 + 512 + d];
    float hr = g_gh[b_*768 + d];
    float hz = g_gh[b_*768 + 256 + d];
    float hn = g_gh[b_*768 + 512 + d];
    float r = 1.f/(1.f + expf(-(xr+hr)));
    float z = 1.f/(1.f + expf(-(xz+hz)));
    float nn = tanhf(xn + r*hn);
    float h = g_hst[b_*DC + d];
    float h2 = (1.f - z)*nn + z*h;
    g_hst[b_*DC + d] = h2;
    g_ctx[bt*DC + d] = h2;
}

// ---------------- output assembly ----------------
__global__ void finalize_k(float* __restrict__ out)
{
    int tid = threadIdx.x;
    for (int i = tid; i < BB*CLIPS; i += blockDim.x) out[i] = (float)g_tok[i];
    for (int i = tid; i < BB*CLIPS*DC; i += blockDim.x) out[28 + i] = g_quant[i];
    if (tid == 0) {
        float c = g_scal[0], x = g_scal[1];
        out[28 + 7168 + 0] = c;
        out[28 + 7168 + 1] = c;
        out[28 + 7168 + 2] = x;
        out[28 + 7168 + 3] = c + 0.25f*c + 0.1f*x;
    }
}

// ---------------- host launcher ----------------
extern "C" void kernel_launch(void* const* d_in, const int* in_sizes, int n_in,
                              void* d_out, int out_size)
{
    const float* x   = (const float*)d_in[0];
    const float* c1w = (const float*)d_in[1];
    const float* c1b = (const float*)d_in[2];
    const float* g1  = (const float*)d_in[3];
    const float* b1  = (const float*)d_in[4];
    const float* c2w = (const float*)d_in[5];
    const float* c2b = (const float*)d_in[6];
    const float* g2  = (const float*)d_in[7];
    const float* b2  = (const float*)d_in[8];
    const float* c3w = (const float*)d_in[9];
    const float* c3b = (const float*)d_in[10];
    const float* g3  = (const float*)d_in[11];
    const float* b3  = (const float*)d_in[12];
    const float* pw  = (const float*)d_in[13];
    const float* pb  = (const float*)d_in[14];
    const float* cb  = (const float*)d_in[15];
    const float* wih = (const float*)d_in[16];
    const float* whh = (const float*)d_in[17];
    const float* bih = (const float*)d_in[18];
    const float* bhh = (const float*)d_in[19];
    float* out = (float*)d_out;

    float *y1, *p1, *y2, *p2, *y3;
    cudaGetSymbolAddress((void**)&y1, g_y1);
    cudaGetSymbolAddress((void**)&p1, g_p1);
    cudaGetSymbolAddress((void**)&y2, g_y2);
    cudaGetSymbolAddress((void**)&p2, g_p2);
    cudaGetSymbolAddress((void**)&y3, g_y3);

    zero_stats_k<<<21,256>>>();

    // ---- stage 1: conv1 [7][4,3,16,96,96] -> [7][4,32,16,96,96]
    conv3d_k<3,32,96,96,8,6,8><<<dim3(12,4,CLIPS*64), dim3(16,8)>>>(
        x, 0L, (long)3*64*96*96, (long)64*96*96, (long)96*96, 8, c1w, c1b, y1);
    stats_k<<<dim3(CLIPS*32,32),256>>>(y1, 0, 32, 16*96*96, (long)32*16*96*96, (long)BB*32*16*96*96);
    finalize_stats_k<<<CLIPS,128>>>(g1, b1, 0, 32, (double)(BB*16*96*96));
    bn_maxpool_k<<<129024,256>>>(y1, p1, 32, 96, 96);

    // ---- stage 2: conv2 -> [7][4,64,16,48,48]
    conv3d_k<32,64,48,48,16,6,8><<<dim3(3,8,CLIPS*64), dim3(8,16)>>>(
        p1, (long)BB*32*16*48*48, (long)32*16*48*48, (long)16*48*48, (long)48*48, 0, c2w, c2b, y2);
    stats_k<<<dim3(CLIPS*64,16),256>>>(y2, 1, 64, 16*48*48, (long)64*16*48*48, (long)BB*64*16*48*48);
    finalize_stats_k<<<CLIPS,128>>>(g2, b2, 1, 64, (double)(BB*16*48*48));
    bn_maxpool_k<<<64512,256>>>(y2, p2, 64, 48, 48);

    // ---- stage 3: conv3 -> [7][4,128,16,24,24]
    conv3d_k<64,128,24,24,24,6,8><<<dim3(1,16,CLIPS*64), dim3(4,24)>>>(
        p2, (long)BB*64*16*24*24, (long)64*16*24*24, (long)16*24*24, (long)24*24, 0, c3w, c3b, y3);
    stats_k<<<dim3(CLIPS*128,8),256>>>(y3, 2, 128, 16*24*24, (long)128*16*24*24, (long)BB*128*16*24*24);
    finalize_stats_k<<<CLIPS,128>>>(g3, b3, 2, 128, (double)(BB*16*24*24));
    bn_avgpool_k<<<3584,256>>>(y3);

    // ---- projection (all 28 rows at once)
    proj_k<<<256,256>>>(pw, pb);

    // ---- VQ + losses + GRU
    quant_score_k<<<dim3(28,32),256>>>(cb);
    quant_reduce_k<<<28,64>>>(cb);
    commit_loss_k<<<1,256>>>();

    gru_gx_k<<<dim3(24,6),128>>>(wih, bih);
    zero_h_k<<<4,256>>>();
    for (int t = 0; t < 6; t++) {
        gru_gh_k<<<dim3(4,6),128>>>(whh, bhh);
        gru_gate_k<<<4,256>>>(t);
    }
    ctx_loss_k<<<1,256>>>();
    finalize_k<<<1,256>>>(out);
}

// round 4
// speedup vs baseline: 1.9326x; 1.7295x over previous
#include <cuda_runtime.h>
#include <math.h>

#define BB 4
#define CF 16
#define CLIPS 7
#define DC 256
#define KC 8192

typedef unsigned long long u64;

__device__ __forceinline__ u64 pk2(float lo, float hi) {
    u64 r; asm("mov.b64 %0,{%1,%2};" : "=l"(r) : "f"(lo), "f"(hi)); return r;
}
__device__ __forceinline__ void upk2(u64 v, float& lo, float& hi) {
    asm("mov.b64 {%0,%1},%2;" : "=f"(lo), "=f"(hi) : "l"(v));
}
__device__ __forceinline__ u64 fma2(u64 a, u64 b, u64 c) {
    u64 r; asm("fma.rn.f32x2 %0,%1,%2,%3;" : "=l"(r) : "l"(a), "l"(b), "l"(c)); return r;
}

// ---------------- scratch ----------------
__device__ float g_y1[CLIPS*BB*32*CF*96*96];
__device__ float g_p1[CLIPS*BB*32*CF*48*48];
__device__ float g_y2[CLIPS*BB*64*CF*48*48];
__device__ float g_p2[CLIPS*BB*64*CF*24*24];
__device__ float g_y3[CLIPS*BB*128*CF*24*24];
__device__ float g_h [CLIPS*BB*32768];
__device__ float g_feat[BB*CLIPS*DC];
__device__ float g_quant[BB*CLIPS*DC];
__device__ int   g_tok[BB*CLIPS];
__device__ double g_stats[3*CLIPS*256];   // [stage][clip][sum(128)|sumsq(128)] ; zero-init; finalize re-zeros
__device__ float g_scale[CLIPS*128];
__device__ float g_shift[CLIPS*128];
__device__ float g_part_s[28*32];
__device__ int   g_part_i[28*32];
__device__ float g_gx[BB*6*768];
__device__ float g_gh[BB*768];
__device__ float g_hst[BB*DC];
__device__ float g_ctx[BB*6*DC];
__device__ float g_scal[2];

// ============ conv3d k=3 pad=1, double-buffered smem, fused BN stats ============
// block: (WS/PW, TH); grid: (HS/TH, COUT/COT, CLIPS*BB*CF)
// WPP: pow2 padded row width >= WS+2.  PW=6 fixed.
template<int CIN, int COUT, int HS, int WS, int TH, int COT, int WPP>
__global__ void conv3d_k(const float* __restrict__ xin, long sclip, long sn, long sc, long sd,
                         int doff, const float* __restrict__ w, const float* __restrict__ bias,
                         float* __restrict__ y, int stage)
{
    constexpr int PW = 6, PH = 3;
    constexpr int NT = (WS/PW)*TH;
    constexpr int NW = NT/32;
    constexpr int RPP = NT/WPP;                      // rows per load pass
    constexpr int PASSES = (TH+2+RPP-1)/RPP;
    constexpr int TILE = (TH+2)*WPP;

    __shared__ __align__(16) float s_x[2][TILE];
    __shared__ __align__(16) float s_w2[2][COT*9*2];
    __shared__ float s_red[NW][COT][2];

    const int tx = threadIdx.x, ty = threadIdx.y;
    const int tid = ty*(WS/PW) + tx;
    const int lane = tid & 31, wid = tid >> 5;
    const int nd = blockIdx.z;
    const int clip = nd >> 6;
    const int n = (nd >> 4) & 3, d = nd & 15;
    const int h0 = blockIdx.x * TH;
    const int co0 = blockIdx.y * COT;

    const int kd0 = (d == 0) ? 1 : 0;
    const int kdn = 3 - kd0 - ((d == CF-1) ? 1 : 0);
    const int P = CIN * kdn;

    // loader geometry (all shifts/masks; WPP pow2)
    const int lc = tid & (WPP-1);
    const int lr0 = tid / WPP;
    const bool colok = (lc >= 1) && (lc <= WS);

    u64 acc2[COT][PH];
    #pragma unroll
    for (int co=0; co<COT; co++)
        #pragma unroll
        for (int j=0; j<PH; j++) acc2[co][j] = 0ULL;

    float rv[PASSES];
    float wv = 0.f;
    const bool wldr = (tid < COT*9);
    const int wco = tid / 9, wk = tid - wco*9;

    // ---- prefetch plane pp into registers
    auto prefetch = [&](int pp) {
        int ci = pp / kdn;
        int kd = kd0 + (pp - ci*kdn);
        int din = d + kd - 1;
        const float* xp = xin + (long)clip*sclip + (long)n*sn + (long)ci*sc
                              + (long)(clip*doff + din)*sd;
        #pragma unroll
        for (int k=0; k<PASSES; k++) {
            int r = k*RPP + lr0;
            int hh = h0 + r - 1;
            float v = 0.f;
            if (r < TH+2 && colok && hh >= 0 && hh < HS)
                v = __ldg(&xp[hh*WS + (lc-1)]);
            rv[k] = v;
        }
        if (wldr)
            wv = __ldg(&w[((long)(co0+wco)*CIN + ci)*27 + kd*9 + wk]);
    };
    // ---- store prefetched regs to smem buffer b
    auto stsbuf = [&](int b) {
        #pragma unroll
        for (int k=0; k<PASSES; k++) {
            int r = k*RPP + lr0;
            if (r < TH+2) s_x[b][r*WPP + lc] = rv[k];
        }
        if (wldr) { s_w2[b][2*tid] = wv; s_w2[b][2*tid+1] = wv; }
    };

    prefetch(0);
    stsbuf(0);
    __syncthreads();

    #pragma unroll 1
    for (int pp = 0; pp < P; pp++) {
        const int b = pp & 1;
        if (pp+1 < P) prefetch(pp+1);
        // ---- compute from buffer b
        #pragma unroll
        for (int kh=0; kh<3; kh++) {
            const float2* x2 = (const float2*)&s_x[b][(ty+kh)*WPP + tx*PW];
            float2 A = x2[0], B = x2[1], C = x2[2], D = x2[3];
            u64 e0 = pk2(A.x, A.y), e1 = pk2(B.x, B.y);
            u64 e2 = pk2(C.x, C.y), e3 = pk2(D.x, D.y);
            u64 o0 = pk2(A.y, B.x), o1 = pk2(B.y, C.x), o2 = pk2(C.y, D.x);
            #pragma unroll
            for (int co=0; co<COT; co++) {
                u64 w0 = *(const u64*)&s_w2[b][2*(co*9 + kh*3 + 0)];
                acc2[co][0] = fma2(w0, e0, acc2[co][0]);
                acc2[co][1] = fma2(w0, e1, acc2[co][1]);
                acc2[co][2] = fma2(w0, e2, acc2[co][2]);
                u64 w1 = *(const u64*)&s_w2[b][2*(co*9 + kh*3 + 1)];
                acc2[co][0] = fma2(w1, o0, acc2[co][0]);
                acc2[co][1] = fma2(w1, o1, acc2[co][1]);
                acc2[co][2] = fma2(w1, o2, acc2[co][2]);
                u64 w2 = *(const u64*)&s_w2[b][2*(co*9 + kh*3 + 2)];
                acc2[co][0] = fma2(w2, e1, acc2[co][0]);
                acc2[co][1] = fma2(w2, e2, acc2[co][1]);
                acc2[co][2] = fma2(w2, e3, acc2[co][2]);
            }
        }
        if (pp+1 < P) stsbuf((pp+1) & 1);
        __syncthreads();
    }

    // ---- epilogue: bias add, store, fused per-channel stats
    const int h = h0 + ty;
    #pragma unroll
    for (int co=0; co<COT; co++) {
        float bv = __ldg(&bias[co0+co]);
        long base = (((long)(clip*BB+n)*COUT + co0+co)*CF + d)*((long)HS*WS) + h*WS + tx*PW;
        float cs = 0.f, cs2 = 0.f;
        #pragma unroll
        for (int j=0; j<PH; j++) {
            float lo, hi; upk2(acc2[co][j], lo, hi);
            lo += bv; hi += bv;
            y[base + 2*j]     = lo;
            y[base + 2*j + 1] = hi;
            cs += lo + hi;
            cs2 = fmaf(lo, lo, fmaf(hi, hi, cs2));
        }
        #pragma unroll
        for (int o=16; o>0; o>>=1) {
            cs  += __shfl_xor_sync(0xffffffff, cs,  o);
            cs2 += __shfl_xor_sync(0xffffffff, cs2, o);
        }
        if (lane == 0) { s_red[wid][co][0] = cs; s_red[wid][co][1] = cs2; }
    }
    __syncthreads();
    if (tid < COT) {
        double ds = 0.0, ds2 = 0.0;
        #pragma unroll
        for (int wi=0; wi<NW; wi++) { ds += (double)s_red[wi][tid][0]; ds2 += (double)s_red[wi][tid][1]; }
        double* st = g_stats + (long)stage*CLIPS*256 + clip*256;
        atomicAdd(&st[co0+tid], ds);
        atomicAdd(&st[128 + co0+tid], ds2);
    }
}

// ---------------- finalize stats (and re-zero accumulators for next replay) ----------------
__global__ void finalize_stats_k(const float* __restrict__ gma, const float* __restrict__ bet,
                                 int stage, int C, double cnt)
{
    int clip = blockIdx.x, c = threadIdx.x;
    if (c < C) {
        double* st = g_stats + (long)stage*CLIPS*256 + clip*256;
        double m = st[c] / cnt;
        double v = st[128 + c] / cnt - m*m;
        st[c] = 0.0; st[128 + c] = 0.0;
        double sc = (double)gma[c] / sqrt(v + 1e-5);
        g_scale[clip*128 + c] = (float)sc;
        g_shift[clip*128 + c] = (float)((double)bet[c] - m*sc);
    }
}

// ---------------- BN + ReLU + maxpool(1,2,2), batched ----------------
__global__ void bn_maxpool_k(const float* __restrict__ y, float* __restrict__ out,
                             int C, int H, int W)
{
    int HO = H/2, WO = W/2;
    long total = (long)CLIPS*BB*C*CF*HO*WO;
    for (long o = (long)blockIdx.x*blockDim.x + threadIdx.x; o < total; o += (long)gridDim.x*blockDim.x) {
        int wo = o % WO; long t = o / WO;
        int ho = t % HO; t /= HO;
        int d  = t % CF; t /= CF;
        int c  = t % C;  t /= C;
        int n  = t % BB; int clip = t / BB;
        float sc = g_scale[clip*128 + c], sh = g_shift[clip*128 + c];
        const float* p = y + (((long)((clip*BB+n)*C + c)*CF + d)*H + 2*ho)*W + 2*wo;
        float a0 = fmaxf(fmaf(sc, p[0],   sh), 0.f);
        float a1 = fmaxf(fmaf(sc, p[1],   sh), 0.f);
        float a2 = fmaxf(fmaf(sc, p[W],   sh), 0.f);
        float a3 = fmaxf(fmaf(sc, p[W+1], sh), 0.f);
        out[o] = fmaxf(fmaxf(a0,a1), fmaxf(a2,a3));
    }
}

// ---------------- BN + ReLU + avgpool 6x6 -> flattened h ----------------
__global__ void bn_avgpool_k(const float* __restrict__ y)
{
    int idx = blockIdx.x*blockDim.x + threadIdx.x;
    if (idx >= CLIPS*BB*128*16*16) return;
    int wo = idx & 3;
    int ho = (idx >> 2) & 3;
    int d  = (idx >> 4) & 15;
    int c  = (idx >> 8) & 127;
    int n  = (idx >> 15) & 3;
    int clip = idx >> 17;
    float sc = g_scale[clip*128 + c], sh = g_shift[clip*128 + c];
    const float* p = y + ((((long)(clip*BB+n)*128 + c)*CF + d)*24 + 6*ho)*24 + 6*wo;
    float s = 0.f;
    #pragma unroll
    for (int i=0;i<6;i++)
        #pragma unroll
        for (int j=0;j<6;j++)
            s += fmaxf(fmaf(sc, p[i*24+j], sh), 0.f);
    g_h[(long)(clip*BB+n)*32768 + c*256 + d*16 + ho*4 + wo] = s * (1.f/36.f);
}

// ---------------- batched projection ----------------
__global__ void proj_k(const float* __restrict__ pw, const float* __restrict__ pb)
{
    int co = blockIdx.x;
    int t = threadIdx.x;
    float part[28];
    #pragma unroll
    for (int r=0;r<28;r++) part[r] = 0.f;
    const float* wrow = pw + (long)co*32768;
    for (int j = t; j < 32768; j += 256) {
        float wv = wrow[j];
        #pragma unroll
        for (int r=0;r<28;r++)
            part[r] = fmaf(wv, g_h[(long)r*32768 + j], part[r]);
    }
    #pragma unroll
    for (int r=0;r<28;r++)
        #pragma unroll
        for (int o=16;o>0;o>>=1)
            part[r] += __shfl_xor_sync(0xffffffff, part[r], o);
    __shared__ float sred[28][8];
    int wa = t >> 5, l = t & 31;
    if (l == 0) {
        #pragma unroll
        for (int r=0;r<28;r++) sred[r][wa] = part[r];
    }
    __syncthreads();
    if (t < 28) {
        float a = 0.f;
        #pragma unroll
        for (int k=0;k<8;k++) a += sred[t][k];
        int clip = t >> 2, b_ = t & 3;
        g_feat[(b_*CLIPS + clip)*DC + co] = a + pb[co];
    }
}

// ---------------- VQ argmin ----------------
__global__ void quant_score_k(const float* __restrict__ cb)
{
    int row = blockIdx.x;
    int k = blockIdx.y*256 + threadIdx.x;
    __shared__ float sf[DC];
    sf[threadIdx.x] = g_feat[row*DC + threadIdx.x];
    __syncthreads();
    const float4* c4 = (const float4*)(cb + (long)k*DC);
    const float4* f4 = (const float4*)sf;
    float dot = 0.f, cn = 0.f;
    #pragma unroll 8
    for (int j=0; j<64; j++) {
        float4 c = c4[j]; float4 f = f4[j];
        dot = fmaf(c.x,f.x,dot); dot = fmaf(c.y,f.y,dot);
        dot = fmaf(c.z,f.z,dot); dot = fmaf(c.w,f.w,dot);
        cn  = fmaf(c.x,c.x,cn);  cn  = fmaf(c.y,c.y,cn);
        cn  = fmaf(c.z,c.z,cn);  cn  = fmaf(c.w,c.w,cn);
    }
    float score = cn - 2.f*dot;
    __shared__ float ss[256];
    __shared__ int   si[256];
    ss[threadIdx.x] = score; si[threadIdx.x] = k;
    __syncthreads();
    for (int o=128; o>0; o>>=1) {
        if (threadIdx.x < o) {
            float s2 = ss[threadIdx.x+o]; int i2 = si[threadIdx.x+o];
            if (s2 < ss[threadIdx.x] || (s2 == ss[threadIdx.x] && i2 < si[threadIdx.x])) {
                ss[threadIdx.x] = s2; si[threadIdx.x] = i2;
            }
        }
        __syncthreads();
    }
    if (threadIdx.x == 0) { g_part_s[row*32+blockIdx.y] = ss[0]; g_part_i[row*32+blockIdx.y] = si[0]; }
}

__global__ void quant_reduce_k(const float* __restrict__ cb)
{
    int row = blockIdx.x;
    __shared__ int bi;
    if (threadIdx.x == 0) {
        float s = g_part_s[row*32]; int i = g_part_i[row*32];
        for (int j=1; j<32; j++) {
            float s2 = g_part_s[row*32+j]; int i2 = g_part_i[row*32+j];
            if (s2 < s || (s2 == s && i2 < i)) { s = s2; i = i2; }
        }
        g_tok[row] = i; bi = i;
    }
    __syncthreads();
    const float* crow = cb + (long)bi*DC;
    for (int j = threadIdx.x; j < DC; j += blockDim.x)
        g_quant[row*DC+j] = crow[j];
}

// ---------------- losses ----------------
__global__ void commit_loss_k()
{
    float s = 0.f;
    for (int i = threadIdx.x; i < BB*CLIPS*DC; i += blockDim.x) {
        float d = g_feat[i] - g_quant[i];
        s = fmaf(d, d, s);
    }
    __shared__ float sh[256];
    sh[threadIdx.x] = s; __syncthreads();
    for (int o=128; o>0; o>>=1) { if (threadIdx.x<o) sh[threadIdx.x]+=sh[threadIdx.x+o]; __syncthreads(); }
    if (threadIdx.x == 0) g_scal[0] = sh[0] / (float)(BB*CLIPS*DC);
}

__global__ void ctx_loss_k()
{
    float s = 0.f;
    for (int i = threadIdx.x; i < BB*6*DC; i += blockDim.x) {
        int d = i % DC; int t = (i/DC) % 6; int b_ = i/(6*DC);
        float diff = g_ctx[i] - g_feat[(b_*CLIPS + t + 1)*DC + d];
        s = fmaf(diff, diff, s);
    }
    __shared__ float sh[256];
    sh[threadIdx.x] = s; __syncthreads();
    for (int o=128; o>0; o>>=1) { if (threadIdx.x<o) sh[threadIdx.x]+=sh[threadIdx.x+o]; __syncthreads(); }
    if (threadIdx.x == 0) g_scal[1] = sh[0] / (float)(BB*6*DC);
}

// ---------------- GRU ----------------
__global__ void gru_gx_k(const float* __restrict__ wih, const float* __restrict__ bih)
{
    int bt = blockIdx.x;
    int g = blockIdx.y*128 + threadIdx.x;
    int b_ = bt/6, t = bt%6;
    __shared__ float sq[DC];
    sq[threadIdx.x]     = g_quant[(b_*CLIPS+t)*DC + threadIdx.x];
    sq[threadIdx.x+128] = g_quant[(b_*CLIPS+t)*DC + 128 + threadIdx.x];
    __syncthreads();
    const float4* w4 = (const float4*)(wih + (long)g*DC);
    const float4* q4 = (const float4*)sq;
    float a = bih[g];
    #pragma unroll 8
    for (int j=0;j<64;j++) {
        float4 w = w4[j], q = q4[j];
        a = fmaf(w.x,q.x,a); a = fmaf(w.y,q.y,a); a = fmaf(w.z,q.z,a); a = fmaf(w.w,q.w,a);
    }
    g_gx[bt*768 + g] = a;
}

__global__ void zero_h_k() {
    int i = blockIdx.x*blockDim.x + threadIdx.x;
    if (i < BB*DC) g_hst[i] = 0.f;
}

__global__ void gru_gh_k(const float* __restrict__ whh, const float* __restrict__ bhh)
{
    int b_ = blockIdx.x;
    int g = blockIdx.y*128 + threadIdx.x;
    __shared__ float shh[DC];
    shh[threadIdx.x]     = g_hst[b_*DC + threadIdx.x];
    shh[threadIdx.x+128] = g_hst[b_*DC + 128 + threadIdx.x];
    __syncthreads();
    const float4* w4 = (const float4*)(whh + (long)g*DC);
    const float4* h4 = (const float4*)shh;
    float a = bhh[g];
    #pragma unroll 8
    for (int j=0;j<64;j++) {
        float4 w = w4[j], h = h4[j];
        a = fmaf(w.x,h.x,a); a = fmaf(w.y,h.y,a); a = fmaf(w.z,h.z,a); a = fmaf(w.w,h.w,a);
    }
    g_gh[b_*768 + g] = a;
}

__global__ void gru_gate_k(int t)
{
    int b_ = blockIdx.x, d = threadIdx.x;
    int bt = b_*6 + t;
    float xr = g_gx[bt*768 + d];
    float xz = g_gx[bt*768 + 256 + d];
    float xn = g_gx[bt*768 + 512 + d];
    float hr = g_gh[b_*768 + d];
    float hz = g_gh[b_*768 + 256 + d];
    float hn = g_gh[b_*768 + 512 + d];
    float r = 1.f/(1.f + expf(-(xr+hr)));
    float z = 1.f/(1.f + expf(-(xz+hz)));
    float nn = tanhf(xn + r*hn);
    float h = g_hst[b_*DC + d];
    float h2 = (1.f - z)*nn + z*h;
    g_hst[b_*DC + d] = h2;
    g_ctx[bt*DC + d] = h2;
}

// ---------------- output assembly ----------------
__global__ void finalize_k(float* __restrict__ out)
{
    int tid = threadIdx.x;
    for (int i = tid; i < BB*CLIPS; i += blockDim.x) out[i] = (float)g_tok[i];
    for (int i = tid; i < BB*CLIPS*DC; i += blockDim.x) out[28 + i] = g_quant[i];
    if (tid == 0) {
        float c = g_scal[0], x = g_scal[1];
        out[28 + 7168 + 0] = c;
        out[28 + 7168 + 1] = c;
        out[28 + 7168 + 2] = x;
        out[28 + 7168 + 3] = c + 0.25f*c + 0.1f*x;
    }
}

// ---------------- host launcher ----------------
extern "C" void kernel_launch(void* const* d_in, const int* in_sizes, int n_in,
                              void* d_out, int out_size)
{
    const float* x   = (const float*)d_in[0];
    const float* c1w = (const float*)d_in[1];
    const float* c1b = (const float*)d_in[2];
    const float* g1  = (const float*)d_in[3];
    const float* b1  = (const float*)d_in[4];
    const float* c2w = (const float*)d_in[5];
    const float* c2b = (const float*)d_in[6];
    const float* g2  = (const float*)d_in[7];
    const float* b2  = (const float*)d_in[8];
    const float* c3w = (const float*)d_in[9];
    const float* c3b = (const float*)d_in[10];
    const float* g3  = (const float*)d_in[11];
    const float* b3  = (const float*)d_in[12];
    const float* pw  = (const float*)d_in[13];
    const float* pb  = (const float*)d_in[14];
    const float* cb  = (const float*)d_in[15];
    const float* wih = (const float*)d_in[16];
    const float* whh = (const float*)d_in[17];
    const float* bih = (const float*)d_in[18];
    const float* bhh = (const float*)d_in[19];
    float* out = (float*)d_out;

    float *y1, *p1, *y2, *p2, *y3;
    cudaGetSymbolAddress((void**)&y1, g_y1);
    cudaGetSymbolAddress((void**)&p1, g_p1);
    cudaGetSymbolAddress((void**)&y2, g_y2);
    cudaGetSymbolAddress((void**)&p2, g_p2);
    cudaGetSymbolAddress((void**)&y3, g_y3);

    // stage 1: conv1 (stats fused)
    conv3d_k<3,32,96,96,8,8,128><<<dim3(12,4,CLIPS*64), dim3(16,8)>>>(
        x, 0L, (long)3*64*96*96, (long)64*96*96, (long)96*96, 8, c1w, c1b, y1, 0);
    finalize_stats_k<<<CLIPS,128>>>(g1, b1, 0, 32, (double)(BB*16*96*96));
    bn_maxpool_k<<<129024,256>>>(y1, p1, 32, 96, 96);

    // stage 2: conv2 (stats fused)  [launch idx 3 -> ncu capture target]
    conv3d_k<32,64,48,48,16,8,64><<<dim3(3,8,CLIPS*64), dim3(8,16)>>>(
        p1, (long)BB*32*16*48*48, (long)32*16*48*48, (long)16*48*48, (long)48*48, 0, c2w, c2b, y2, 1);
    finalize_stats_k<<<CLIPS,128>>>(g2, b2, 1, 64, (double)(BB*16*48*48));
    bn_maxpool_k<<<64512,256>>>(y2, p2, 64, 48, 48);

    // stage 3: conv3 (stats fused)
    conv3d_k<64,128,24,24,24,8,32><<<dim3(1,16,CLIPS*64), dim3(4,24)>>>(
        p2, (long)BB*64*16*24*24, (long)64*16*24*24, (long)16*24*24, (long)24*24, 0, c3w, c3b, y3, 2);
    finalize_stats_k<<<CLIPS,128>>>(g3, b3, 2, 128, (double)(BB*16*24*24));
    bn_avgpool_k<<<3584,256>>>(y3);

    // projection + VQ + losses + GRU
    proj_k<<<256,256>>>(pw, pb);
    quant_score_k<<<dim3(28,32),256>>>(cb);
    quant_reduce_k<<<28,64>>>(cb);
    commit_loss_k<<<1,256>>>();

    gru_gx_k<<<dim3(24,6),128>>>(wih, bih);
    zero_h_k<<<4,256>>>();
    for (int t = 0; t < 6; t++) {
        gru_gh_k<<<dim3(4,6),128>>>(whh, bhh);
        gru_gate_k<<<4,256>>>(t);
    }
    ctx_loss_k<<<1,256>>>();
    finalize_k<<<1,256>>>(out);
}